// round 12
// baseline (speedup 1.0000x reference)
#include <cuda_runtime.h>
#include <cuda_bf16.h>
#include <cstdint>

// Problem constants
#define BB  16
#define TT  12
#define NN  1024
#define DD  512
#define HH  8
#define HD  64
#define CC  128
#define BTT (BB*TT)          // 192
#define MQ  (BTT*NN)         // 196608
#define MKV (BTT*CC)         // 24576

// ---------------- device scratch (no allocations allowed) ----------------
__device__ float g_q [(size_t)MQ  * DD];   // scaled q (fp32)
__device__ float g_ao[(size_t)MQ  * DD];   // attention output (fp32)
__device__ float g_xp[(size_t)MKV * DD];   // pooled x
__device__ float g_k [(size_t)MKV * DD];   // pooled k
__device__ float g_v [(size_t)MKV * DD];   // pooled v

// ---------------- helpers ----------------
__device__ __forceinline__ unsigned smem_u32(const void* p) {
    return (unsigned)__cvta_generic_to_shared(p);
}

// split two floats into packed bf16 hi pair + bf16 lo pair (residual)
__device__ __forceinline__ void split_pack(float x0, float x1, unsigned& hi, unsigned& lo) {
    __nv_bfloat162 h2 = __floats2bfloat162_rn(x0, x1);
    float r0 = x0 - __bfloat162float(h2.x);
    float r1 = x1 - __bfloat162float(h2.y);
    __nv_bfloat162 l2 = __floats2bfloat162_rn(r0, r1);
    hi = *reinterpret_cast<unsigned*>(&h2);
    lo = *reinterpret_cast<unsigned*>(&l2);
}

__device__ __forceinline__ void split1(float x, unsigned short& h, unsigned short& l) {
    __nv_bfloat16 bh = __float2bfloat16(x);
    float r = x - __bfloat162float(bh);
    __nv_bfloat16 bl = __float2bfloat16(r);
    h = *reinterpret_cast<unsigned short*>(&bh);
    l = *reinterpret_cast<unsigned short*>(&bl);
}

__device__ __forceinline__ void ldm_x4(unsigned& r0, unsigned& r1, unsigned& r2, unsigned& r3, unsigned addr) {
    asm volatile("ldmatrix.sync.aligned.m8n8.x4.shared.b16 {%0,%1,%2,%3}, [%4];"
                 : "=r"(r0), "=r"(r1), "=r"(r2), "=r"(r3) : "r"(addr));
}
__device__ __forceinline__ void ldm_x2(unsigned& r0, unsigned& r1, unsigned addr) {
    asm volatile("ldmatrix.sync.aligned.m8n8.x2.shared.b16 {%0,%1}, [%2];"
                 : "=r"(r0), "=r"(r1) : "r"(addr));
}
__device__ __forceinline__ void mma_acc(float* c, const unsigned* a, unsigned b0, unsigned b1) {
    asm volatile("mma.sync.aligned.m16n8k16.row.col.f32.bf16.bf16.f32 "
                 "{%0,%1,%2,%3}, {%4,%5,%6,%7}, {%8,%9}, {%0,%1,%2,%3};"
                 : "+f"(c[0]), "+f"(c[1]), "+f"(c[2]), "+f"(c[3])
                 : "r"(a[0]), "r"(a[1]), "r"(a[2]), "r"(a[3]), "r"(b0), "r"(b1));
}

// ---------------- pooling: xp[bt,c,d] = mean_j x[bt, c*8+j, d] ----------------
__global__ void pool_kernel(const float* __restrict__ x, float* __restrict__ xp) {
    int idx = blockIdx.x * blockDim.x + threadIdx.x;   // over MKV*DD/4 float4s
    if (idx >= MKV * DD / 4) return;
    int d4  = idx & (DD / 4 - 1);     // 0..127
    int btc = idx >> 7;
    int bt  = btc / CC, c = btc % CC;
    const float4* base = (const float4*)x;
    float4 s = make_float4(0.f, 0.f, 0.f, 0.f);
#pragma unroll
    for (int j = 0; j < 8; j++) {
        float4 v = base[(size_t)(bt * NN + c * 8 + j) * (DD / 4) + d4];
        s.x += v.x; s.y += v.y; s.z += v.z; s.w += v.w;
    }
    s.x *= 0.125f; s.y *= 0.125f; s.z *= 0.125f; s.w *= 0.125f;
    ((float4*)xp)[idx] = s;
}

// ---------------- split-bf16 GEMM: C[M,512] = (A[M,512] @ W[512,512] + bias) * scale ----------------
#define BK   32
#define APAD 8
#define ASTR (BK + APAD)   // 40 bf16 -> 80B row stride, conflict-free ldmatrix

__global__ __launch_bounds__(256, 2)
void gemm_split(const float* __restrict__ A, const float* __restrict__ W,
                const float* __restrict__ bias, float* __restrict__ Cout, float scale) {
    __shared__ unsigned short sAh[128][ASTR], sAl[128][ASTR];
    __shared__ unsigned short sBh[128][ASTR], sBl[128][ASTR];  // W transposed: [n][k]

    const int tid  = threadIdx.x;
    const int lane = tid & 31, warp = tid >> 5;
    const int wm = warp >> 1, wn = warp & 1;       // 4 x 2 warp grid, warp tile 32x64
    const int m0 = blockIdx.y * 128;
    const int n0 = blockIdx.x * 128;

    float acc[2][8][4];
#pragma unroll
    for (int i = 0; i < 2; i++)
#pragma unroll
        for (int j = 0; j < 8; j++) { acc[i][j][0] = 0.f; acc[i][j][1] = 0.f; acc[i][j][2] = 0.f; acc[i][j][3] = 0.f; }

    const int ar  = tid >> 3, ac4 = tid & 7;       // A: 32 rows/pass, 8 float4 per row
    const int wkk = tid >> 5, wc4 = tid & 31;      // W: 8 k-rows/pass, 32 float4 per row

    for (int k0 = 0; k0 < DD; k0 += BK) {
        // load + split A tile [128 x 32]
#pragma unroll
        for (int p = 0; p < 4; p++) {
            int r = ar + p * 32;
            float4 v = *(const float4*)&A[(size_t)(m0 + r) * DD + k0 + ac4 * 4];
            unsigned h01, l01, h23, l23;
            split_pack(v.x, v.y, h01, l01);
            split_pack(v.z, v.w, h23, l23);
            *(uint2*)&sAh[r][ac4 * 4] = make_uint2(h01, h23);
            *(uint2*)&sAl[r][ac4 * 4] = make_uint2(l01, l23);
        }
        // load + split + transpose W tile [32 x 128] -> [n][k]
#pragma unroll
        for (int p = 0; p < 4; p++) {
            int kk = wkk + p * 8;
            float4 v = *(const float4*)&W[(size_t)(k0 + kk) * DD + n0 + wc4 * 4];
            unsigned short h, l;
            split1(v.x, h, l); sBh[wc4 * 4 + 0][kk] = h; sBl[wc4 * 4 + 0][kk] = l;
            split1(v.y, h, l); sBh[wc4 * 4 + 1][kk] = h; sBl[wc4 * 4 + 1][kk] = l;
            split1(v.z, h, l); sBh[wc4 * 4 + 2][kk] = h; sBl[wc4 * 4 + 2][kk] = l;
            split1(v.w, h, l); sBh[wc4 * 4 + 3][kk] = h; sBl[wc4 * 4 + 3][kk] = l;
        }
        __syncthreads();

#pragma unroll
        for (int ks = 0; ks < 2; ks++) {
            unsigned ah[2][4], al[2][4];
#pragma unroll
            for (int mt = 0; mt < 2; mt++) {
                int rr = wm * 32 + mt * 16 + (lane & 15);
                int cc = ks * 16 + (lane >> 4) * 8;
                ldm_x4(ah[mt][0], ah[mt][1], ah[mt][2], ah[mt][3], smem_u32(&sAh[rr][cc]));
                ldm_x4(al[mt][0], al[mt][1], al[mt][2], al[mt][3], smem_u32(&sAl[rr][cc]));
            }
#pragma unroll
            for (int nt = 0; nt < 8; nt++) {
                int rr = wn * 64 + nt * 8 + (lane & 7);
                int cc = ks * 16 + ((lane >> 3) & 1) * 8;
                unsigned bh0, bh1, bl0, bl1;
                ldm_x2(bh0, bh1, smem_u32(&sBh[rr][cc]));
                ldm_x2(bl0, bl1, smem_u32(&sBl[rr][cc]));
#pragma unroll
                for (int mt = 0; mt < 2; mt++) {
                    mma_acc(acc[mt][nt], ah[mt], bh0, bh1);   // hi*hi
                    mma_acc(acc[mt][nt], ah[mt], bl0, bl1);   // hi*lo
                    mma_acc(acc[mt][nt], al[mt], bh0, bh1);   // lo*hi
                }
            }
        }
        __syncthreads();
    }

    // epilogue: (+bias)*scale, fp32 out
#pragma unroll
    for (int mt = 0; mt < 2; mt++) {
        int row = m0 + wm * 32 + mt * 16 + (lane >> 2);
#pragma unroll
        for (int nt = 0; nt < 8; nt++) {
            int col = n0 + wn * 64 + nt * 8 + (lane & 3) * 2;
            float b0 = bias[col], b1 = bias[col + 1];
            float2 v0 = make_float2((acc[mt][nt][0] + b0) * scale, (acc[mt][nt][1] + b1) * scale);
            float2 v1 = make_float2((acc[mt][nt][2] + b0) * scale, (acc[mt][nt][3] + b1) * scale);
            *(float2*)&Cout[(size_t)row * DD + col]       = v0;
            *(float2*)&Cout[(size_t)(row + 8) * DD + col] = v1;
        }
    }
}

// ---------------- fused attention ----------------
// grid: (N/128, H, BT); block 256 threads (8 warps, 16 q-rows per warp)
#define QPAD 8
#define QSTR (HD + QPAD)   // 72
#define VSTR (CC + QPAD)   // 136
#define ATTN_SMEM ((4 * 128 * QSTR + 2 * 64 * VSTR) * 2)   // 108544 bytes

__global__ __launch_bounds__(256)
void attn_kernel(const float* __restrict__ q, const float* __restrict__ k,
                 const float* __restrict__ v, const float* __restrict__ adp,
                 float* __restrict__ out) {
    extern __shared__ unsigned short sm[];
    unsigned short* p = sm;
    unsigned short (*sQh)[QSTR] = (unsigned short(*)[QSTR])p; p += 128 * QSTR;
    unsigned short (*sQl)[QSTR] = (unsigned short(*)[QSTR])p; p += 128 * QSTR;
    unsigned short (*sKh)[QSTR] = (unsigned short(*)[QSTR])p; p += 128 * QSTR;
    unsigned short (*sKl)[QSTR] = (unsigned short(*)[QSTR])p; p += 128 * QSTR;
    unsigned short (*sVh)[VSTR] = (unsigned short(*)[VSTR])p; p += 64 * VSTR;   // V transposed [d][c]
    unsigned short (*sVl)[VSTR] = (unsigned short(*)[VSTR])p;

    const int tid = threadIdx.x, lane = tid & 31, warp = tid >> 5;
    const int n0 = blockIdx.x * 128;
    const int h  = blockIdx.y;
    const int bt = blockIdx.z;

    const int lr = tid >> 4, lc4 = tid & 15;   // 16 rows/pass, 16 float4 per row
#pragma unroll
    for (int pp = 0; pp < 8; pp++) {
        int r = lr + pp * 16;
        // Q (already pre-scaled by 1/sqrt(HD))
        float4 vq = *(const float4*)&q[(size_t)(bt * NN + n0 + r) * DD + h * HD + lc4 * 4];
        unsigned h01, l01, h23, l23;
        split_pack(vq.x, vq.y, h01, l01); split_pack(vq.z, vq.w, h23, l23);
        *(uint2*)&sQh[r][lc4 * 4] = make_uint2(h01, h23);
        *(uint2*)&sQl[r][lc4 * 4] = make_uint2(l01, l23);
        // K
        size_t koff = (size_t)(bt * CC + r) * DD + h * HD + lc4 * 4;
        float4 vk = *(const float4*)&k[koff];
        split_pack(vk.x, vk.y, h01, l01); split_pack(vk.z, vk.w, h23, l23);
        *(uint2*)&sKh[r][lc4 * 4] = make_uint2(h01, h23);
        *(uint2*)&sKl[r][lc4 * 4] = make_uint2(l01, l23);
        // V transposed
        float4 vv = *(const float4*)&v[koff];
        unsigned short hh, ll;
        split1(vv.x, hh, ll); sVh[lc4 * 4 + 0][r] = hh; sVl[lc4 * 4 + 0][r] = ll;
        split1(vv.y, hh, ll); sVh[lc4 * 4 + 1][r] = hh; sVl[lc4 * 4 + 1][r] = ll;
        split1(vv.z, hh, ll); sVh[lc4 * 4 + 2][r] = hh; sVl[lc4 * 4 + 2][r] = ll;
        split1(vv.w, hh, ll); sVh[lc4 * 4 + 3][r] = hh; sVl[lc4 * 4 + 3][r] = ll;
    }
    __syncthreads();

    // S = Q*K^T : warp owns rows [warp*16, warp*16+16), all 128 cols
    float S[16][4];
#pragma unroll
    for (int nt = 0; nt < 16; nt++) { S[nt][0] = 0.f; S[nt][1] = 0.f; S[nt][2] = 0.f; S[nt][3] = 0.f; }

#pragma unroll
    for (int ks = 0; ks < 4; ks++) {
        unsigned ah[4], al[4];
        {
            int rr = warp * 16 + (lane & 15);
            int cc = ks * 16 + (lane >> 4) * 8;
            ldm_x4(ah[0], ah[1], ah[2], ah[3], smem_u32(&sQh[rr][cc]));
            ldm_x4(al[0], al[1], al[2], al[3], smem_u32(&sQl[rr][cc]));
        }
#pragma unroll
        for (int nt = 0; nt < 16; nt++) {
            int rr = nt * 8 + (lane & 7);
            int cc = ks * 16 + ((lane >> 3) & 1) * 8;
            unsigned bh0, bh1, bl0, bl1;
            ldm_x2(bh0, bh1, smem_u32(&sKh[rr][cc]));
            ldm_x2(bl0, bl1, smem_u32(&sKl[rr][cc]));
            mma_acc(S[nt], ah, bh0, bh1);
            mma_acc(S[nt], ah, bl0, bl1);
            mma_acc(S[nt], al, bh0, bh1);
        }
    }

    // bias + softmax (rows g and g+8; quad = lanes sharing a row)
    const int g = lane >> 2, tq = lane & 3;
    const int rowg = n0 + warp * 16 + g;
    float mx0 = -1e30f, mx1 = -1e30f;
#pragma unroll
    for (int nt = 0; nt < 16; nt++) {
        float2 b0 = __ldg((const float2*)&adp[(size_t)rowg * CC + nt * 8 + tq * 2]);
        float2 b1 = __ldg((const float2*)&adp[(size_t)(rowg + 8) * CC + nt * 8 + tq * 2]);
        S[nt][0] += b0.x; S[nt][1] += b0.y; S[nt][2] += b1.x; S[nt][3] += b1.y;
        mx0 = fmaxf(mx0, fmaxf(S[nt][0], S[nt][1]));
        mx1 = fmaxf(mx1, fmaxf(S[nt][2], S[nt][3]));
    }
    mx0 = fmaxf(mx0, __shfl_xor_sync(0xffffffffu, mx0, 1));
    mx0 = fmaxf(mx0, __shfl_xor_sync(0xffffffffu, mx0, 2));
    mx1 = fmaxf(mx1, __shfl_xor_sync(0xffffffffu, mx1, 1));
    mx1 = fmaxf(mx1, __shfl_xor_sync(0xffffffffu, mx1, 2));
    float sum0 = 0.f, sum1 = 0.f;
#pragma unroll
    for (int nt = 0; nt < 16; nt++) {
        S[nt][0] = __expf(S[nt][0] - mx0); sum0 += S[nt][0];
        S[nt][1] = __expf(S[nt][1] - mx0); sum0 += S[nt][1];
        S[nt][2] = __expf(S[nt][2] - mx1); sum1 += S[nt][2];
        S[nt][3] = __expf(S[nt][3] - mx1); sum1 += S[nt][3];
    }
    sum0 += __shfl_xor_sync(0xffffffffu, sum0, 1);
    sum0 += __shfl_xor_sync(0xffffffffu, sum0, 2);
    sum1 += __shfl_xor_sync(0xffffffffu, sum1, 1);
    sum1 += __shfl_xor_sync(0xffffffffu, sum1, 2);
    float r0 = 1.f / sum0, r1 = 1.f / sum1;
#pragma unroll
    for (int nt = 0; nt < 16; nt++) {
        S[nt][0] *= r0; S[nt][1] *= r0; S[nt][2] *= r1; S[nt][3] *= r1;
    }

    // O = P * V   (P fragments built straight from S registers, hi/lo split)
    float O[8][4];
#pragma unroll
    for (int nt = 0; nt < 8; nt++) { O[nt][0] = 0.f; O[nt][1] = 0.f; O[nt][2] = 0.f; O[nt][3] = 0.f; }

#pragma unroll
    for (int ks = 0; ks < 8; ks++) {
        unsigned ph[4], pl[4];
        split_pack(S[2 * ks][0],     S[2 * ks][1],     ph[0], pl[0]);
        split_pack(S[2 * ks][2],     S[2 * ks][3],     ph[1], pl[1]);
        split_pack(S[2 * ks + 1][0], S[2 * ks + 1][1], ph[2], pl[2]);
        split_pack(S[2 * ks + 1][2], S[2 * ks + 1][3], ph[3], pl[3]);
#pragma unroll
        for (int nt = 0; nt < 8; nt++) {
            int rr = nt * 8 + (lane & 7);
            int cc = ks * 16 + ((lane >> 3) & 1) * 8;
            unsigned bh0, bh1, bl0, bl1;
            ldm_x2(bh0, bh1, smem_u32(&sVh[rr][cc]));
            ldm_x2(bl0, bl1, smem_u32(&sVl[rr][cc]));
            mma_acc(O[nt], ph, bh0, bh1);
            mma_acc(O[nt], ph, bl0, bl1);
            mma_acc(O[nt], pl, bh0, bh1);
        }
    }

    // write merged-head output
#pragma unroll
    for (int nt = 0; nt < 8; nt++) {
        int col = h * HD + nt * 8 + tq * 2;
        *(float2*)&out[(size_t)(bt * NN + rowg) * DD + col]     = make_float2(O[nt][0], O[nt][1]);
        *(float2*)&out[(size_t)(bt * NN + rowg + 8) * DD + col] = make_float2(O[nt][2], O[nt][3]);
    }
}

// ---------------- launch ----------------
extern "C" void kernel_launch(void* const* d_in, const int* in_sizes, int n_in,
                              void* d_out, int out_size) {
    const float* x   = (const float*)d_in[0];
    const float* Wq  = (const float*)d_in[1];
    const float* bq  = (const float*)d_in[2];
    const float* Wk  = (const float*)d_in[3];
    const float* bk  = (const float*)d_in[4];
    const float* Wv  = (const float*)d_in[5];
    const float* bv  = (const float*)d_in[6];
    const float* Wo  = (const float*)d_in[7];
    const float* bo  = (const float*)d_in[8];
    const float* adp = (const float*)d_in[9];
    float* out = (float*)d_out;

    float *qp, *aop, *xpp, *kp, *vp;
    cudaGetSymbolAddress((void**)&qp,  g_q);
    cudaGetSymbolAddress((void**)&aop, g_ao);
    cudaGetSymbolAddress((void**)&xpp, g_xp);
    cudaGetSymbolAddress((void**)&kp,  g_k);
    cudaGetSymbolAddress((void**)&vp,  g_v);

    cudaFuncSetAttribute(attn_kernel, cudaFuncAttributeMaxDynamicSharedMemorySize, ATTN_SMEM);

    // 1) pooled x (linearity: pool before k/v projections)
    pool_kernel<<<(MKV * DD / 4 + 255) / 256, 256>>>(x, xpp);
    // 2) q = (x@Wq + bq) / sqrt(HD)
    gemm_split<<<dim3(4, MQ / 128), 256>>>(x, Wq, bq, qp, 0.125f);
    // 3) k, v on pooled x
    gemm_split<<<dim3(4, MKV / 128), 256>>>(xpp, Wk, bk, kp, 1.0f);
    gemm_split<<<dim3(4, MKV / 128), 256>>>(xpp, Wv, bv, vp, 1.0f);
    // 4) fused attention
    attn_kernel<<<dim3(NN / 128, HH, BTT), 256, ATTN_SMEM>>>(qp, kp, vp, adp, aop);
    // 5) output projection
    gemm_split<<<dim3(4, MQ / 128), 256>>>(aop, Wo, bo, out, 1.0f);
}

// round 13
// speedup vs baseline: 1.0010x; 1.0010x over previous
#include <cuda_runtime.h>
#include <cuda_bf16.h>
#include <cstdint>

// Problem constants
#define BB  16
#define TT  12
#define NN  1024
#define DD  512
#define HH  8
#define HD  64
#define CC  128
#define BTT (BB*TT)          // 192
#define MQ  (BTT*NN)         // 196608
#define MKV (BTT*CC)         // 24576

// ---------------- device scratch (no allocations allowed) ----------------
__device__ float g_q [(size_t)MQ  * DD];   // scaled q (fp32)
__device__ float g_ao[(size_t)MQ  * DD];   // attention output (fp32)
__device__ float g_xp[(size_t)MKV * DD];   // pooled x
__device__ float g_k [(size_t)MKV * DD];   // pooled k
__device__ float g_v [(size_t)MKV * DD];   // pooled v

// ---------------- helpers ----------------
__device__ __forceinline__ unsigned smem_u32(const void* p) {
    return (unsigned)__cvta_generic_to_shared(p);
}

// split two floats into packed bf16 hi pair + bf16 lo pair (residual)
__device__ __forceinline__ void split_pack(float x0, float x1, unsigned& hi, unsigned& lo) {
    __nv_bfloat162 h2 = __floats2bfloat162_rn(x0, x1);
    float r0 = x0 - __bfloat162float(h2.x);
    float r1 = x1 - __bfloat162float(h2.y);
    __nv_bfloat162 l2 = __floats2bfloat162_rn(r0, r1);
    hi = *reinterpret_cast<unsigned*>(&h2);
    lo = *reinterpret_cast<unsigned*>(&l2);
}

__device__ __forceinline__ void split1(float x, unsigned short& h, unsigned short& l) {
    __nv_bfloat16 bh = __float2bfloat16(x);
    float r = x - __bfloat162float(bh);
    __nv_bfloat16 bl = __float2bfloat16(r);
    h = *reinterpret_cast<unsigned short*>(&bh);
    l = *reinterpret_cast<unsigned short*>(&bl);
}

__device__ __forceinline__ void ldm_x4(unsigned& r0, unsigned& r1, unsigned& r2, unsigned& r3, unsigned addr) {
    asm volatile("ldmatrix.sync.aligned.m8n8.x4.shared.b16 {%0,%1,%2,%3}, [%4];"
                 : "=r"(r0), "=r"(r1), "=r"(r2), "=r"(r3) : "r"(addr));
}
__device__ __forceinline__ void ldm_x2(unsigned& r0, unsigned& r1, unsigned addr) {
    asm volatile("ldmatrix.sync.aligned.m8n8.x2.shared.b16 {%0,%1}, [%2];"
                 : "=r"(r0), "=r"(r1) : "r"(addr));
}
__device__ __forceinline__ void mma_acc(float* c, const unsigned* a, unsigned b0, unsigned b1) {
    asm volatile("mma.sync.aligned.m16n8k16.row.col.f32.bf16.bf16.f32 "
                 "{%0,%1,%2,%3}, {%4,%5,%6,%7}, {%8,%9}, {%0,%1,%2,%3};"
                 : "+f"(c[0]), "+f"(c[1]), "+f"(c[2]), "+f"(c[3])
                 : "r"(a[0]), "r"(a[1]), "r"(a[2]), "r"(a[3]), "r"(b0), "r"(b1));
}

// ---------------- pooling: xp[bt,c,d] = mean_j x[bt, c*8+j, d] ----------------
__global__ void pool_kernel(const float* __restrict__ x, float* __restrict__ xp) {
    int idx = blockIdx.x * blockDim.x + threadIdx.x;   // over MKV*DD/4 float4s
    if (idx >= MKV * DD / 4) return;
    int d4  = idx & (DD / 4 - 1);     // 0..127
    int btc = idx >> 7;
    int bt  = btc / CC, c = btc % CC;
    const float4* base = (const float4*)x;
    float4 s = make_float4(0.f, 0.f, 0.f, 0.f);
#pragma unroll
    for (int j = 0; j < 8; j++) {
        float4 v = base[(size_t)(bt * NN + c * 8 + j) * (DD / 4) + d4];
        s.x += v.x; s.y += v.y; s.z += v.z; s.w += v.w;
    }
    s.x *= 0.125f; s.y *= 0.125f; s.z *= 0.125f; s.w *= 0.125f;
    ((float4*)xp)[idx] = s;
}

// ---------------- split-bf16 GEMM: C[M,512] = (A[M,512] @ W[512,512] + bias) * scale ----------------
#define BK   32
#define APAD 8
#define ASTR (BK + APAD)   // 40 bf16 -> 80B row stride, conflict-free ldmatrix

__global__ __launch_bounds__(256, 2)
void gemm_split(const float* __restrict__ A, const float* __restrict__ W,
                const float* __restrict__ bias, float* __restrict__ Cout, float scale) {
    __shared__ unsigned short sAh[128][ASTR], sAl[128][ASTR];
    __shared__ unsigned short sBh[128][ASTR], sBl[128][ASTR];  // W transposed: [n][k]

    const int tid  = threadIdx.x;
    const int lane = tid & 31, warp = tid >> 5;
    const int wm = warp >> 1, wn = warp & 1;       // 4 x 2 warp grid, warp tile 32x64
    const int m0 = blockIdx.y * 128;
    const int n0 = blockIdx.x * 128;

    float acc[2][8][4];
#pragma unroll
    for (int i = 0; i < 2; i++)
#pragma unroll
        for (int j = 0; j < 8; j++) { acc[i][j][0] = 0.f; acc[i][j][1] = 0.f; acc[i][j][2] = 0.f; acc[i][j][3] = 0.f; }

    const int ar  = tid >> 3, ac4 = tid & 7;       // A: 32 rows/pass, 8 float4 per row
    const int wkk = tid >> 5, wc4 = tid & 31;      // W: 8 k-rows/pass, 32 float4 per row

    for (int k0 = 0; k0 < DD; k0 += BK) {
        // load + split A tile [128 x 32]
#pragma unroll
        for (int p = 0; p < 4; p++) {
            int r = ar + p * 32;
            float4 v = *(const float4*)&A[(size_t)(m0 + r) * DD + k0 + ac4 * 4];
            unsigned h01, l01, h23, l23;
            split_pack(v.x, v.y, h01, l01);
            split_pack(v.z, v.w, h23, l23);
            *(uint2*)&sAh[r][ac4 * 4] = make_uint2(h01, h23);
            *(uint2*)&sAl[r][ac4 * 4] = make_uint2(l01, l23);
        }
        // load + split + transpose W tile [32 x 128] -> [n][k]
#pragma unroll
        for (int p = 0; p < 4; p++) {
            int kk = wkk + p * 8;
            float4 v = *(const float4*)&W[(size_t)(k0 + kk) * DD + n0 + wc4 * 4];
            unsigned short h, l;
            split1(v.x, h, l); sBh[wc4 * 4 + 0][kk] = h; sBl[wc4 * 4 + 0][kk] = l;
            split1(v.y, h, l); sBh[wc4 * 4 + 1][kk] = h; sBl[wc4 * 4 + 1][kk] = l;
            split1(v.z, h, l); sBh[wc4 * 4 + 2][kk] = h; sBl[wc4 * 4 + 2][kk] = l;
            split1(v.w, h, l); sBh[wc4 * 4 + 3][kk] = h; sBl[wc4 * 4 + 3][kk] = l;
        }
        __syncthreads();

#pragma unroll
        for (int ks = 0; ks < 2; ks++) {
            unsigned ah[2][4], al[2][4];
#pragma unroll
            for (int mt = 0; mt < 2; mt++) {
                int rr = wm * 32 + mt * 16 + (lane & 15);
                int cc = ks * 16 + (lane >> 4) * 8;
                ldm_x4(ah[mt][0], ah[mt][1], ah[mt][2], ah[mt][3], smem_u32(&sAh[rr][cc]));
                ldm_x4(al[mt][0], al[mt][1], al[mt][2], al[mt][3], smem_u32(&sAl[rr][cc]));
            }
#pragma unroll
            for (int nt = 0; nt < 8; nt++) {
                int rr = wn * 64 + nt * 8 + (lane & 7);
                int cc = ks * 16 + ((lane >> 3) & 1) * 8;
                unsigned bh0, bh1, bl0, bl1;
                ldm_x2(bh0, bh1, smem_u32(&sBh[rr][cc]));
                ldm_x2(bl0, bl1, smem_u32(&sBl[rr][cc]));
#pragma unroll
                for (int mt = 0; mt < 2; mt++) {
                    mma_acc(acc[mt][nt], ah[mt], bh0, bh1);   // hi*hi
                    mma_acc(acc[mt][nt], ah[mt], bl0, bl1);   // hi*lo
                    mma_acc(acc[mt][nt], al[mt], bh0, bh1);   // lo*hi
                }
            }
        }
        __syncthreads();
    }

    // epilogue: (+bias)*scale, fp32 out
#pragma unroll
    for (int mt = 0; mt < 2; mt++) {
        int row = m0 + wm * 32 + mt * 16 + (lane >> 2);
#pragma unroll
        for (int nt = 0; nt < 8; nt++) {
            int col = n0 + wn * 64 + nt * 8 + (lane & 3) * 2;
            float b0 = bias[col], b1 = bias[col + 1];
            float2 v0 = make_float2((acc[mt][nt][0] + b0) * scale, (acc[mt][nt][1] + b1) * scale);
            float2 v1 = make_float2((acc[mt][nt][2] + b0) * scale, (acc[mt][nt][3] + b1) * scale);
            *(float2*)&Cout[(size_t)row * DD + col]       = v0;
            *(float2*)&Cout[(size_t)(row + 8) * DD + col] = v1;
        }
    }
}

// ---------------- fused attention ----------------
// grid: (N/128, H, BT); block 256 threads (8 warps, 16 q-rows per warp)
#define QPAD 8
#define QSTR (HD + QPAD)   // 72
#define VSTR (CC + QPAD)   // 136
#define ATTN_SMEM ((4 * 128 * QSTR + 2 * 64 * VSTR) * 2)   // 108544 bytes

__global__ __launch_bounds__(256)
void attn_kernel(const float* __restrict__ q, const float* __restrict__ k,
                 const float* __restrict__ v, const float* __restrict__ adp,
                 float* __restrict__ out) {
    extern __shared__ unsigned short sm[];
    unsigned short* p = sm;
    unsigned short (*sQh)[QSTR] = (unsigned short(*)[QSTR])p; p += 128 * QSTR;
    unsigned short (*sQl)[QSTR] = (unsigned short(*)[QSTR])p; p += 128 * QSTR;
    unsigned short (*sKh)[QSTR] = (unsigned short(*)[QSTR])p; p += 128 * QSTR;
    unsigned short (*sKl)[QSTR] = (unsigned short(*)[QSTR])p; p += 128 * QSTR;
    unsigned short (*sVh)[VSTR] = (unsigned short(*)[VSTR])p; p += 64 * VSTR;   // V transposed [d][c]
    unsigned short (*sVl)[VSTR] = (unsigned short(*)[VSTR])p;

    const int tid = threadIdx.x, lane = tid & 31, warp = tid >> 5;
    const int n0 = blockIdx.x * 128;
    const int h  = blockIdx.y;
    const int bt = blockIdx.z;

    const int lr = tid >> 4, lc4 = tid & 15;   // 16 rows/pass, 16 float4 per row
#pragma unroll
    for (int pp = 0; pp < 8; pp++) {
        int r = lr + pp * 16;
        // Q (already pre-scaled by 1/sqrt(HD))
        float4 vq = *(const float4*)&q[(size_t)(bt * NN + n0 + r) * DD + h * HD + lc4 * 4];
        unsigned h01, l01, h23, l23;
        split_pack(vq.x, vq.y, h01, l01); split_pack(vq.z, vq.w, h23, l23);
        *(uint2*)&sQh[r][lc4 * 4] = make_uint2(h01, h23);
        *(uint2*)&sQl[r][lc4 * 4] = make_uint2(l01, l23);
        // K
        size_t koff = (size_t)(bt * CC + r) * DD + h * HD + lc4 * 4;
        float4 vk = *(const float4*)&k[koff];
        split_pack(vk.x, vk.y, h01, l01); split_pack(vk.z, vk.w, h23, l23);
        *(uint2*)&sKh[r][lc4 * 4] = make_uint2(h01, h23);
        *(uint2*)&sKl[r][lc4 * 4] = make_uint2(l01, l23);
        // V transposed
        float4 vv = *(const float4*)&v[koff];
        unsigned short hh, ll;
        split1(vv.x, hh, ll); sVh[lc4 * 4 + 0][r] = hh; sVl[lc4 * 4 + 0][r] = ll;
        split1(vv.y, hh, ll); sVh[lc4 * 4 + 1][r] = hh; sVl[lc4 * 4 + 1][r] = ll;
        split1(vv.z, hh, ll); sVh[lc4 * 4 + 2][r] = hh; sVl[lc4 * 4 + 2][r] = ll;
        split1(vv.w, hh, ll); sVh[lc4 * 4 + 3][r] = hh; sVl[lc4 * 4 + 3][r] = ll;
    }
    __syncthreads();

    // S = Q*K^T : warp owns rows [warp*16, warp*16+16), all 128 cols
    float S[16][4];
#pragma unroll
    for (int nt = 0; nt < 16; nt++) { S[nt][0] = 0.f; S[nt][1] = 0.f; S[nt][2] = 0.f; S[nt][3] = 0.f; }

#pragma unroll
    for (int ks = 0; ks < 4; ks++) {
        unsigned ah[4], al[4];
        {
            int rr = warp * 16 + (lane & 15);
            int cc = ks * 16 + (lane >> 4) * 8;
            ldm_x4(ah[0], ah[1], ah[2], ah[3], smem_u32(&sQh[rr][cc]));
            ldm_x4(al[0], al[1], al[2], al[3], smem_u32(&sQl[rr][cc]));
        }
#pragma unroll
        for (int nt = 0; nt < 16; nt++) {
            int rr = nt * 8 + (lane & 7);
            int cc = ks * 16 + ((lane >> 3) & 1) * 8;
            unsigned bh0, bh1, bl0, bl1;
            ldm_x2(bh0, bh1, smem_u32(&sKh[rr][cc]));
            ldm_x2(bl0, bl1, smem_u32(&sKl[rr][cc]));
            mma_acc(S[nt], ah, bh0, bh1);
            mma_acc(S[nt], ah, bl0, bl1);
            mma_acc(S[nt], al, bh0, bh1);
        }
    }

    // bias + softmax (rows g and g+8; quad = lanes sharing a row)
    const int g = lane >> 2, tq = lane & 3;
    const int rowg = n0 + warp * 16 + g;
    float mx0 = -1e30f, mx1 = -1e30f;
#pragma unroll
    for (int nt = 0; nt < 16; nt++) {
        float2 b0 = __ldg((const float2*)&adp[(size_t)rowg * CC + nt * 8 + tq * 2]);
        float2 b1 = __ldg((const float2*)&adp[(size_t)(rowg + 8) * CC + nt * 8 + tq * 2]);
        S[nt][0] += b0.x; S[nt][1] += b0.y; S[nt][2] += b1.x; S[nt][3] += b1.y;
        mx0 = fmaxf(mx0, fmaxf(S[nt][0], S[nt][1]));
        mx1 = fmaxf(mx1, fmaxf(S[nt][2], S[nt][3]));
    }
    mx0 = fmaxf(mx0, __shfl_xor_sync(0xffffffffu, mx0, 1));
    mx0 = fmaxf(mx0, __shfl_xor_sync(0xffffffffu, mx0, 2));
    mx1 = fmaxf(mx1, __shfl_xor_sync(0xffffffffu, mx1, 1));
    mx1 = fmaxf(mx1, __shfl_xor_sync(0xffffffffu, mx1, 2));
    float sum0 = 0.f, sum1 = 0.f;
#pragma unroll
    for (int nt = 0; nt < 16; nt++) {
        S[nt][0] = __expf(S[nt][0] - mx0); sum0 += S[nt][0];
        S[nt][1] = __expf(S[nt][1] - mx0); sum0 += S[nt][1];
        S[nt][2] = __expf(S[nt][2] - mx1); sum1 += S[nt][2];
        S[nt][3] = __expf(S[nt][3] - mx1); sum1 += S[nt][3];
    }
    sum0 += __shfl_xor_sync(0xffffffffu, sum0, 1);
    sum0 += __shfl_xor_sync(0xffffffffu, sum0, 2);
    sum1 += __shfl_xor_sync(0xffffffffu, sum1, 1);
    sum1 += __shfl_xor_sync(0xffffffffu, sum1, 2);
    float r0 = 1.f / sum0, r1 = 1.f / sum1;
#pragma unroll
    for (int nt = 0; nt < 16; nt++) {
        S[nt][0] *= r0; S[nt][1] *= r0; S[nt][2] *= r1; S[nt][3] *= r1;
    }

    // O = P * V   (P fragments built straight from S registers, hi/lo split)
    float O[8][4];
#pragma unroll
    for (int nt = 0; nt < 8; nt++) { O[nt][0] = 0.f; O[nt][1] = 0.f; O[nt][2] = 0.f; O[nt][3] = 0.f; }

#pragma unroll
    for (int ks = 0; ks < 8; ks++) {
        unsigned ph[4], pl[4];
        split_pack(S[2 * ks][0],     S[2 * ks][1],     ph[0], pl[0]);
        split_pack(S[2 * ks][2],     S[2 * ks][3],     ph[1], pl[1]);
        split_pack(S[2 * ks + 1][0], S[2 * ks + 1][1], ph[2], pl[2]);
        split_pack(S[2 * ks + 1][2], S[2 * ks + 1][3], ph[3], pl[3]);
#pragma unroll
        for (int nt = 0; nt < 8; nt++) {
            int rr = nt * 8 + (lane & 7);
            int cc = ks * 16 + ((lane >> 3) & 1) * 8;
            unsigned bh0, bh1, bl0, bl1;
            ldm_x2(bh0, bh1, smem_u32(&sVh[rr][cc]));
            ldm_x2(bl0, bl1, smem_u32(&sVl[rr][cc]));
            mma_acc(O[nt], ph, bh0, bh1);
            mma_acc(O[nt], ph, bl0, bl1);
            mma_acc(O[nt], pl, bh0, bh1);
        }
    }

    // write merged-head output
#pragma unroll
    for (int nt = 0; nt < 8; nt++) {
        int col = h * HD + nt * 8 + tq * 2;
        *(float2*)&out[(size_t)(bt * NN + rowg) * DD + col]     = make_float2(O[nt][0], O[nt][1]);
        *(float2*)&out[(size_t)(bt * NN + rowg + 8) * DD + col] = make_float2(O[nt][2], O[nt][3]);
    }
}

// ---------------- launch ----------------
extern "C" void kernel_launch(void* const* d_in, const int* in_sizes, int n_in,
                              void* d_out, int out_size) {
    const float* x   = (const float*)d_in[0];
    const float* Wq  = (const float*)d_in[1];
    const float* bq  = (const float*)d_in[2];
    const float* Wk  = (const float*)d_in[3];
    const float* bk  = (const float*)d_in[4];
    const float* Wv  = (const float*)d_in[5];
    const float* bv  = (const float*)d_in[6];
    const float* Wo  = (const float*)d_in[7];
    const float* bo  = (const float*)d_in[8];
    const float* adp = (const float*)d_in[9];
    float* out = (float*)d_out;

    float *qp, *aop, *xpp, *kp, *vp;
    cudaGetSymbolAddress((void**)&qp,  g_q);
    cudaGetSymbolAddress((void**)&aop, g_ao);
    cudaGetSymbolAddress((void**)&xpp, g_xp);
    cudaGetSymbolAddress((void**)&kp,  g_k);
    cudaGetSymbolAddress((void**)&vp,  g_v);

    cudaFuncSetAttribute(attn_kernel, cudaFuncAttributeMaxDynamicSharedMemorySize, ATTN_SMEM);

    // 1) pooled x (linearity: pool before k/v projections)
    pool_kernel<<<(MKV * DD / 4 + 255) / 256, 256>>>(x, xpp);
    // 2) q = (x@Wq + bq) / sqrt(HD)
    gemm_split<<<dim3(4, MQ / 128), 256>>>(x, Wq, bq, qp, 0.125f);
    // 3) k, v on pooled x
    gemm_split<<<dim3(4, MKV / 128), 256>>>(xpp, Wk, bk, kp, 1.0f);
    gemm_split<<<dim3(4, MKV / 128), 256>>>(xpp, Wv, bv, vp, 1.0f);
    // 4) fused attention
    attn_kernel<<<dim3(NN / 128, HH, BTT), 256, ATTN_SMEM>>>(qp, kp, vp, adp, aop);
    // 5) output projection
    gemm_split<<<dim3(4, MQ / 128), 256>>>(aop, Wo, bo, out, 1.0f);
}